// round 4
// baseline (speedup 1.0000x reference)
#include <cuda_runtime.h>
#include <math.h>
#include <stdint.h>

#define BATCH 32
#define DEPTH 12
#define CDIM 768
#define NHEADS 12
#define HD 64
#define NTOK 197
#define NPATCH 196
#define GRD 14
#define PSZ 16
#define HIDDIM 3072
#define NCLS 1000
#define IMG 224
#define HALFW 3

// ---------------- scratch (device globals; no allocation allowed) -------------
__device__ float g_xp[BATCH * NPATCH * CDIM];
__device__ float g_t[BATCH * NTOK * CDIM];
__device__ float g_h[BATCH * NTOK * CDIM];
__device__ float g_qkv[BATCH * NTOK * 3 * CDIM];
__device__ float g_o[BATCH * NTOK * CDIM];
__device__ float g_mlp[BATCH * NTOK * HIDDIM];
__device__ float g_cls[BATCH * CDIM];

// ================= TF32 tensor-core GEMM, cp.async 3-stage pipeline ==========
#define TCBM 128
#define TCBN 128
#define TCBK 16
#define ASTR (TCBK + 4)
#define BSTR (TCBN + 4)
#define NSTAGE 3

__device__ __forceinline__ uint32_t f2tf32(float x) {
    uint32_t r;
    asm("cvt.rna.tf32.f32 %0, %1;" : "=r"(r) : "f"(x));
    return r;
}

__device__ __forceinline__ void mma_tf32(float* d, const uint32_t* a, const uint32_t* b) {
    asm volatile(
        "mma.sync.aligned.m16n8k8.row.col.f32.tf32.tf32.f32 "
        "{%0,%1,%2,%3}, {%4,%5,%6,%7}, {%8,%9}, {%0,%1,%2,%3};"
        : "+f"(d[0]), "+f"(d[1]), "+f"(d[2]), "+f"(d[3])
        : "r"(a[0]), "r"(a[1]), "r"(a[2]), "r"(a[3]), "r"(b[0]), "r"(b[1]));
}

__device__ __forceinline__ void cp16(uint32_t dst_smem, const void* src, int size) {
    asm volatile("cp.async.cg.shared.global [%0], [%1], 16, %2;\n"
                 :: "r"(dst_smem), "l"(src), "r"(size));
}
__device__ __forceinline__ void cp_commit() {
    asm volatile("cp.async.commit_group;\n");
}
template <int NWAIT>
__device__ __forceinline__ void cp_wait() {
    asm volatile("cp.async.wait_group %0;\n" :: "n"(NWAIT));
}

template <bool BT, bool GELU>
__global__ void __launch_bounds__(256, 2)
gemm_tc(int M, int N, int K,
        const float* __restrict__ A, const float* __restrict__ B,
        const float* __restrict__ bias, const float* __restrict__ resid,
        float* __restrict__ C) {
    __shared__ uint32_t As[NSTAGE][TCBM][ASTR];
    __shared__ uint32_t Bs[NSTAGE][BT ? (TCBM * ASTR) : (TCBK * BSTR)];

    const int tid = threadIdx.x;
    const int lane = tid & 31;
    const int warp = tid >> 5;
    const int m0 = blockIdx.y * TCBM;
    const int n0 = blockIdx.x * TCBN;
    const int wm = (warp >> 2) * 64;
    const int wn = (warp & 3) * 32;
    const int r = lane >> 2;
    const int c = lane & 3;

    float acc[4][4][4];
#pragma unroll
    for (int mt = 0; mt < 4; mt++)
#pragma unroll
        for (int nt = 0; nt < 4; nt++)
#pragma unroll
            for (int i = 0; i < 4; i++) acc[mt][nt][i] = 0.f;

    const int iters = K / TCBK;

    auto load_stage = [&](int stage, int k0) {
#pragma unroll
        for (int j = 0; j < 2; j++) {
            int ci = tid + j * 256;
            int m = ci >> 2;
            int kc = (ci & 3) << 2;
            int gm = m0 + m;
            uint32_t dst = (uint32_t)__cvta_generic_to_shared(&As[stage][m][kc]);
            const float* src = &A[(size_t)gm * K + k0 + kc];
            cp16(dst, src, (gm < M) ? 16 : 0);
        }
        if (!BT) {
#pragma unroll
            for (int j = 0; j < 2; j++) {
                int ci = tid + j * 256;
                int k = ci >> 5;
                int nc = (ci & 31) << 2;
                uint32_t dst = (uint32_t)__cvta_generic_to_shared(&Bs[stage][k * BSTR + nc]);
                const float* src = &B[(size_t)(k0 + k) * N + n0 + nc];
                cp16(dst, src, 16);
            }
        } else {
#pragma unroll
            for (int j = 0; j < 2; j++) {
                int ci = tid + j * 256;
                int n = ci >> 2;
                int kc = (ci & 3) << 2;
                uint32_t dst = (uint32_t)__cvta_generic_to_shared(&Bs[stage][n * ASTR + kc]);
                const float* src = &B[(size_t)(n0 + n) * K + k0 + kc];
                cp16(dst, src, 16);
            }
        }
    };

    // prologue: stages 0,1
    load_stage(0, 0);
    cp_commit();
    if (iters > 1) load_stage(1, TCBK);
    cp_commit();

    int buf = 0;
    for (int it = 0; it < iters; ++it) {
        cp_wait<1>();          // group for stage `it` guaranteed complete
        __syncthreads();

#pragma unroll
        for (int ks = 0; ks < TCBK; ks += 8) {
            uint32_t af[4][4], bf[4][2];
#pragma unroll
            for (int mt = 0; mt < 4; mt++) {
                int mb = wm + mt * 16 + r;
                af[mt][0] = f2tf32(__uint_as_float(As[buf][mb][ks + c]));
                af[mt][1] = f2tf32(__uint_as_float(As[buf][mb + 8][ks + c]));
                af[mt][2] = f2tf32(__uint_as_float(As[buf][mb][ks + c + 4]));
                af[mt][3] = f2tf32(__uint_as_float(As[buf][mb + 8][ks + c + 4]));
            }
#pragma unroll
            for (int nt = 0; nt < 4; nt++) {
                int nb = wn + nt * 8 + r;
                if (!BT) {
                    bf[nt][0] = f2tf32(__uint_as_float(Bs[buf][(ks + c) * BSTR + nb]));
                    bf[nt][1] = f2tf32(__uint_as_float(Bs[buf][(ks + c + 4) * BSTR + nb]));
                } else {
                    bf[nt][0] = f2tf32(__uint_as_float(Bs[buf][nb * ASTR + ks + c]));
                    bf[nt][1] = f2tf32(__uint_as_float(Bs[buf][nb * ASTR + ks + c + 4]));
                }
            }
#pragma unroll
            for (int mt = 0; mt < 4; mt++)
#pragma unroll
                for (int nt = 0; nt < 4; nt++)
                    mma_tf32(acc[mt][nt], af[mt], bf[nt]);
        }
        __syncthreads();   // all warps done with stage buf before it is refilled

        if (it + 2 < iters) {
            int nb2 = buf + 2;
            if (nb2 >= NSTAGE) nb2 -= NSTAGE;
            load_stage(nb2, (it + 2) * TCBK);
        }
        cp_commit();       // always commit (empty group in drain phase)

        buf = (buf == NSTAGE - 1) ? 0 : buf + 1;
    }

    // ---- epilogue ----
#pragma unroll
    for (int mt = 0; mt < 4; mt++) {
#pragma unroll
        for (int half = 0; half < 2; half++) {
            int gm = m0 + wm + mt * 16 + r + half * 8;
            if (gm >= M) continue;
#pragma unroll
            for (int nt = 0; nt < 4; nt++) {
                int gn = n0 + wn + nt * 8 + c * 2;
                float v0 = acc[mt][nt][half * 2 + 0];
                float v1 = acc[mt][nt][half * 2 + 1];
                if (bias) {
                    v0 += bias[gn];
                    v1 += bias[gn + 1];
                }
                if (GELU) {
                    v0 = 0.5f * v0 * (1.f + erff(v0 * 0.70710678118654752f));
                    v1 = 0.5f * v1 * (1.f + erff(v1 * 0.70710678118654752f));
                }
                if (resid) {
                    const float2 rr = *reinterpret_cast<const float2*>(
                        &resid[(size_t)gm * N + gn]);
                    v0 += rr.x;
                    v1 += rr.y;
                }
                *reinterpret_cast<float2*>(&C[(size_t)gm * N + gn]) =
                    make_float2(v0, v1);
            }
        }
    }
}

// ---------------- small SIMT GEMM (head: M=32, N=1000) ------------------------
#define BM 128
#define BN 128
#define BK 8
#define TM 8
#define TN 8

__global__ void __launch_bounds__(256)
gemm_small(int M, int N, int K,
           const float* __restrict__ A, const float* __restrict__ B,
           const float* __restrict__ bias, float* __restrict__ C) {
    __shared__ float As[BK][BM];
    __shared__ float Bs[BK][BN];
    const int tid = threadIdx.x;
    const int m0 = blockIdx.y * BM;
    const int n0 = blockIdx.x * BN;
    const int tx = tid % (BN / TN);
    const int ty = tid / (BN / TN);

    float acc[TM][TN];
#pragma unroll
    for (int i = 0; i < TM; i++)
#pragma unroll
        for (int j = 0; j < TN; j++) acc[i][j] = 0.f;

    const int arow = tid / (BK / 4);
    const int acol = (tid % (BK / 4)) * 4;
    const int brow = tid / (BN / 4);
    const int bcol = (tid % (BN / 4)) * 4;

    for (int k0 = 0; k0 < K; k0 += BK) {
        {
            int gm = m0 + arow;
            float4 v = make_float4(0.f, 0.f, 0.f, 0.f);
            if (gm < M)
                v = *reinterpret_cast<const float4*>(&A[(size_t)gm * K + k0 + acol]);
            As[acol + 0][arow] = v.x;
            As[acol + 1][arow] = v.y;
            As[acol + 2][arow] = v.z;
            As[acol + 3][arow] = v.w;
        }
        {
            int gn = n0 + bcol;
            float t0 = (gn + 0 < N) ? B[(size_t)(k0 + brow) * N + gn + 0] : 0.f;
            float t1 = (gn + 1 < N) ? B[(size_t)(k0 + brow) * N + gn + 1] : 0.f;
            float t2 = (gn + 2 < N) ? B[(size_t)(k0 + brow) * N + gn + 2] : 0.f;
            float t3 = (gn + 3 < N) ? B[(size_t)(k0 + brow) * N + gn + 3] : 0.f;
            Bs[brow][bcol + 0] = t0;
            Bs[brow][bcol + 1] = t1;
            Bs[brow][bcol + 2] = t2;
            Bs[brow][bcol + 3] = t3;
        }
        __syncthreads();
#pragma unroll
        for (int kk = 0; kk < BK; kk++) {
            float ra[TM], rb[TN];
#pragma unroll
            for (int i = 0; i < TM; i++) ra[i] = As[kk][ty * TM + i];
#pragma unroll
            for (int j = 0; j < TN; j++) rb[j] = Bs[kk][tx * TN + j];
#pragma unroll
            for (int i = 0; i < TM; i++)
#pragma unroll
                for (int j = 0; j < TN; j++) acc[i][j] = fmaf(ra[i], rb[j], acc[i][j]);
        }
        __syncthreads();
    }
#pragma unroll
    for (int i = 0; i < TM; i++) {
        int gm = m0 + ty * TM + i;
        if (gm >= M) continue;
#pragma unroll
        for (int j = 0; j < TN; j++) {
            int gn = n0 + tx * TN + j;
            if (gn >= N) continue;
            float v = acc[i][j];
            if (bias) v += bias[gn];
            C[(size_t)gm * N + gn] = v;
        }
    }
}

// ---------------- patch gather -----------------------------------------------
__global__ void gather_kernel(const float* __restrict__ x) {
    int idx = blockIdx.x * blockDim.x + threadIdx.x;
    const int total = BATCH * NPATCH * CDIM;
    if (idx >= total) return;
    int k = idx % CDIM;
    int g = (idx / CDIM) % NPATCH;
    int b = idx / (CDIM * NPATCH);
    int ch = k / (PSZ * PSZ);
    int pr = (k / PSZ) % PSZ;
    int pc = k % PSZ;
    int gr = g / GRD;
    int gc = g % GRD;
    g_xp[idx] = x[(((size_t)b * 3 + ch) * IMG + gr * PSZ + pr) * IMG + gc * PSZ + pc];
}

// ---------------- assemble t = [cls; patches] + pos --------------------------
__global__ void assemble_kernel(const float* __restrict__ cls_tok,
                                const float* __restrict__ pos) {
    int idx = blockIdx.x * blockDim.x + threadIdx.x;
    const int total = BATCH * NTOK * CDIM;
    if (idx >= total) return;
    int c = idx % CDIM;
    int n = (idx / CDIM) % NTOK;
    int b = idx / (CDIM * NTOK);
    float v = (n == 0) ? cls_tok[c] : g_h[((size_t)b * NPATCH + n - 1) * CDIM + c];
    g_t[idx] = v + pos[(size_t)n * CDIM + c];
}

// ---------------- layernorm (warp-shuffle reduction) --------------------------
__global__ void __launch_bounds__(256)
ln_kernel(const float* __restrict__ x, long in_stride,
          const float* __restrict__ w, const float* __restrict__ b,
          float* __restrict__ y, long out_stride) {
    const float* row = x + (size_t)blockIdx.x * in_stride;
    float* out = y + (size_t)blockIdx.x * out_stride;
    int tid = threadIdx.x;
    float v0 = row[tid], v1 = row[tid + 256], v2 = row[tid + 512];
    float s = v0 + v1 + v2;
    float s2 = v0 * v0 + v1 * v1 + v2 * v2;
#pragma unroll
    for (int o = 16; o > 0; o >>= 1) {
        s += __shfl_xor_sync(0xffffffffu, s, o);
        s2 += __shfl_xor_sync(0xffffffffu, s2, o);
    }
    __shared__ float ps[8], ps2[8];
    if ((tid & 31) == 0) {
        ps[tid >> 5] = s;
        ps2[tid >> 5] = s2;
    }
    __syncthreads();
    float ts = ps[tid & 7], ts2 = ps2[tid & 7];
#pragma unroll
    for (int o = 4; o > 0; o >>= 1) {
        ts += __shfl_xor_sync(0xffffffffu, ts, o);
        ts2 += __shfl_xor_sync(0xffffffffu, ts2, o);
    }
    float mu = ts * (1.f / CDIM);
    float var = ts2 * (1.f / CDIM) - mu * mu;
    float rstd = rsqrtf(var + 1e-5f);
    out[tid] = (v0 - mu) * rstd * w[tid] + b[tid];
    out[tid + 256] = (v1 - mu) * rstd * w[tid + 256] + b[tid + 256];
    out[tid + 512] = (v2 - mu) * rstd * w[tid + 512] + b[tid + 512];
}

// ---------------- fused flash attention --------------------------------------
// grid (7, NHEADS, BATCH), 256 threads. 32 queries/block, 32-key tiles.
#define FBQ 32
#define FBK 32

__device__ __forceinline__ bool attn_allowed(int q, int k) {
    if (q == 0 || k == 0) return true;
    int qr = (q - 1) / GRD, qc = (q - 1) % GRD;
    int kr = (k - 1) / GRD, kc = (k - 1) % GRD;
    return (abs(qr - kr) <= HALFW) && (abs(qc - kc) <= HALFW);
}

__global__ void __launch_bounds__(256)
flash_kernel() {
    const int b = blockIdx.z;
    const int h = blockIdx.y;
    const int q0 = blockIdx.x * FBQ;
    const int tid = threadIdx.x;

    __shared__ float Qs[FBQ][HD + 1];
    __shared__ float Ks[FBK][HD + 1];
    __shared__ float Vs[FBK][HD + 1];
    __shared__ float Ps[FBQ][FBK + 1];

    const float* qkv = g_qkv;
    const size_t rowstride = 3 * CDIM;

    // load Q tile
    for (int idx = tid; idx < FBQ * HD; idx += 256) {
        int q = idx >> 6, d = idx & 63;
        int gq = q0 + q;
        Qs[q][d] = (gq < NTOK)
            ? qkv[((size_t)(b * NTOK + gq)) * rowstride + h * HD + d] : 0.f;
    }

    // key range from local mask (contiguous for non-cls queries)
    int klo = 0, khi = NTOK - 1;
    bool full = (q0 == 0);  // cls query present -> all keys
    if (!full) {
        int qlo = q0, qhi = min(q0 + FBQ - 1, NTOK - 1);
        int qr_min = (qlo - 1) / GRD, qr_max = (qhi - 1) / GRD;
        klo = 1 + max(0, qr_min - HALFW) * GRD;
        khi = min(NTOK - 1, (qr_max + HALFW) * GRD + GRD);
    }

    const int q = tid >> 3;        // 0..31 : my query
    const int j = tid & 7;         // 0..7
    const int gq = q0 + q;
    const bool qvalid = (gq < NTOK);
    const int dbase = j * 8;       // my 8 output dims

    float m_old = -INFINITY, l = 0.f;
    float acc[8];
#pragma unroll
    for (int i = 0; i < 8; i++) acc[i] = 0.f;

    for (int kt = 0; kt < (NTOK + FBK - 1) / FBK; kt++) {
        int kbase = kt * FBK;
        if (!(kt == 0 || full || (kbase + FBK - 1 >= klo && kbase <= khi)))
            continue;

        __syncthreads();
        // load K,V tiles
        for (int idx = tid; idx < FBK * HD; idx += 256) {
            int kk = idx >> 6, d = idx & 63;
            int gk = kbase + kk;
            if (gk < NTOK) {
                Ks[kk][d] = qkv[((size_t)(b * NTOK + gk)) * rowstride + CDIM + h * HD + d];
                Vs[kk][d] = qkv[((size_t)(b * NTOK + gk)) * rowstride + 2 * CDIM + h * HD + d];
            } else {
                Ks[kk][d] = 0.f;
                Vs[kk][d] = 0.f;
            }
        }
        __syncthreads();

        // scores: my 4 key columns kc = j + 8*i
        float s[4];
#pragma unroll
        for (int i = 0; i < 4; i++) {
            int kc = j + i * 8;
            float a = 0.f;
#pragma unroll
            for (int d = 0; d < HD; d++) a = fmaf(Qs[q][d], Ks[kc][d], a);
            a *= 0.125f;
            int gk = kbase + kc;
            if (!qvalid || gk >= NTOK || !attn_allowed(gq, gk)) a = -INFINITY;
            s[i] = a;
        }
        // row max over 8 lanes
        float mt = fmaxf(fmaxf(s[0], s[1]), fmaxf(s[2], s[3]));
#pragma unroll
        for (int o = 1; o < 8; o <<= 1)
            mt = fmaxf(mt, __shfl_xor_sync(0xffffffffu, mt, o));
        float m_new = fmaxf(m_old, mt);
        float scale = (m_new == -INFINITY) ? 1.f : __expf(m_old - m_new);
        float psum = 0.f;
#pragma unroll
        for (int i = 0; i < 4; i++) {
            float p = (s[i] == -INFINITY) ? 0.f : __expf(s[i] - m_new);
            Ps[q][j + i * 8] = p;
            psum += p;
        }
#pragma unroll
        for (int o = 1; o < 8; o <<= 1)
            psum += __shfl_xor_sync(0xffffffffu, psum, o);
        l = l * scale + psum;
        m_old = m_new;
        __syncwarp();

        // PV accumulate (acc scaled first)
#pragma unroll
        for (int i = 0; i < 8; i++) acc[i] *= scale;
        for (int kk = 0; kk < FBK; kk++) {
            float p = Ps[q][kk];
#pragma unroll
            for (int i = 0; i < 8; i++)
                acc[i] = fmaf(p, Vs[kk][dbase + i], acc[i]);
        }
        __syncwarp();
    }

    if (qvalid) {
        float inv = 1.f / l;
#pragma unroll
        for (int i = 0; i < 8; i++)
            g_o[((size_t)(b * NTOK + gq)) * CDIM + h * HD + dbase + i] = acc[i] * inv;
    }
}

// ---------------- launch helpers ---------------------------------------------
static inline dim3 tc_grid(int M, int N) {
    return dim3((N + TCBN - 1) / TCBN, (M + TCBM - 1) / TCBM);
}

extern "C" void kernel_launch(void* const* d_in, const int* in_sizes, int n_in,
                              void* d_out, int out_size) {
    const float* x       = (const float*)d_in[0];
    const float* patch_w = (const float*)d_in[1];
    const float* patch_b = (const float*)d_in[2];
    const float* cls_tok = (const float*)d_in[3];
    const float* pos     = (const float*)d_in[4];
    const float* ln1_w   = (const float*)d_in[5];
    const float* ln1_b   = (const float*)d_in[6];
    const float* qkv_w   = (const float*)d_in[7];
    const float* proj_w  = (const float*)d_in[8];
    const float* proj_b  = (const float*)d_in[9];
    const float* ln2_w   = (const float*)d_in[10];
    const float* ln2_b   = (const float*)d_in[11];
    const float* mlp_w1  = (const float*)d_in[12];
    const float* mlp_b1  = (const float*)d_in[13];
    const float* mlp_w2  = (const float*)d_in[14];
    const float* mlp_b2  = (const float*)d_in[15];
    const float* norm_w  = (const float*)d_in[16];
    const float* norm_b  = (const float*)d_in[17];
    const float* head_w  = (const float*)d_in[18];
    const float* head_b  = (const float*)d_in[19];
    float* out = (float*)d_out;

    float *xp, *t, *h, *qkv, *o, *mlp, *cls;
    cudaGetSymbolAddress((void**)&xp, g_xp);
    cudaGetSymbolAddress((void**)&t, g_t);
    cudaGetSymbolAddress((void**)&h, g_h);
    cudaGetSymbolAddress((void**)&qkv, g_qkv);
    cudaGetSymbolAddress((void**)&o, g_o);
    cudaGetSymbolAddress((void**)&mlp, g_mlp);
    cudaGetSymbolAddress((void**)&cls, g_cls);

    const int Mtok = BATCH * NTOK;  // 6304

    // patch embed
    {
        int total = BATCH * NPATCH * CDIM;
        gather_kernel<<<(total + 255) / 256, 256>>>(x);
        gemm_tc<true, false><<<tc_grid(BATCH * NPATCH, CDIM), 256>>>(
            BATCH * NPATCH, CDIM, CDIM, xp, patch_w, patch_b, nullptr, h);
        int tot2 = BATCH * NTOK * CDIM;
        assemble_kernel<<<(tot2 + 255) / 256, 256>>>(cls_tok, pos);
    }

    for (int i = 0; i < DEPTH; i++) {
        ln_kernel<<<Mtok, 256>>>(t, CDIM, ln1_w + i * CDIM, ln1_b + i * CDIM, h, CDIM);
        gemm_tc<false, false><<<tc_grid(Mtok, 3 * CDIM), 256>>>(
            Mtok, 3 * CDIM, CDIM, h, qkv_w + (size_t)i * CDIM * 3 * CDIM,
            nullptr, nullptr, qkv);
        flash_kernel<<<dim3((NTOK + FBQ - 1) / FBQ, NHEADS, BATCH), 256>>>();
        gemm_tc<false, false><<<tc_grid(Mtok, CDIM), 256>>>(
            Mtok, CDIM, CDIM, o, proj_w + (size_t)i * CDIM * CDIM,
            proj_b + i * CDIM, t, t);
        ln_kernel<<<Mtok, 256>>>(t, CDIM, ln2_w + i * CDIM, ln2_b + i * CDIM, h, CDIM);
        gemm_tc<false, true><<<tc_grid(Mtok, HIDDIM), 256>>>(
            Mtok, HIDDIM, CDIM, h, mlp_w1 + (size_t)i * CDIM * HIDDIM,
            mlp_b1 + i * HIDDIM, nullptr, mlp);
        gemm_tc<false, false><<<tc_grid(Mtok, CDIM), 256>>>(
            Mtok, CDIM, HIDDIM, mlp, mlp_w2 + (size_t)i * HIDDIM * CDIM,
            mlp_b2 + i * CDIM, t, t);
    }

    ln_kernel<<<BATCH, 256>>>(t, (long)NTOK * CDIM, norm_w, norm_b, cls, CDIM);
    gemm_small<<<dim3((NCLS + BN - 1) / BN, 1), 256>>>(
        BATCH, NCLS, CDIM, cls, head_w, head_b, out);
}